// round 16
// baseline (speedup 1.0000x reference)
#include <cuda_runtime.h>
#include <cstdint>

// SpottingLoss: greedy bipartite matching + YOLO-style loss.
// B=2048 batches, N=64 slots, F=19 features.
// R15: TWO batches per warp, software-pipelined. Both batches' tiles are
//   staged via cp.async up front (one commit group per batch); batch B's
//   DRAM latency is fully hidden under batch A's matching+epilogue, so the
//   startup stall is paid once per TWO batches. Block count halves (256),
//   halving tail atomics again. Matching core is byte-identical to R14.
// Kept: phase-1 elimination, poison free-set (pmneg=-3), f32x2+IMNMX scan,
//   32-bit native ATOMS.MIN acceptance, lane-compacted proposals, pure-LDS
//   epilogue, per-block reduction + acq_rel ticket finalize.

#define N_ 64
#define F_ 19
#define TILE_FLOATS (N_ * F_)             // 1216 floats = 4864 B per tile
#define TILE_CHUNKS (TILE_FLOATS / 4)     // 304 x 16B per tile
#define WPB 4                             // warps per 128-thread block
#define BPW 2                             // batches per warp (pipelined)
#define LAMBDA_COORD 5.0f
#define LAMBDA_NOOBJ 0.5f
#define FULLM 0xFFFFFFFFu
#define POISON_BITS 0xC0400000u           // -3.0f

// Grid-reduction scratch. Zero-initialized at module load; the LAST block of
// every launch resets both, so each graph replay starts clean.
__device__ float    g_acc   = 0.0f;
__device__ unsigned g_count = 0u;

__device__ __forceinline__ void cp_async16(uint32_t smem_dst, const void* gsrc) {
    asm volatile("cp.async.cg.shared.global [%0], [%1], 16;"
                 :: "r"(smem_dst), "l"(gsrc) : "memory");
}
__device__ __forceinline__ unsigned long long f32x2_add(unsigned long long a,
                                                        unsigned long long b) {
    unsigned long long r;
    asm("add.rn.f32x2 %0, %1, %2;" : "=l"(r) : "l"(a), "l"(b));
    return r;
}

struct __align__(16) Tiles {
    float yt[TILE_FLOATS];    // y_true tile
    float yp[TILE_FLOATS];    // y_pred tile
};
struct __align__(16) MatchState {
    float pmneg[N_];          // -p while free; -3.0f poison once taken
    unsigned colkey[N_];      // 32-bit acceptance keys (native ATOMS.MIN.U32)
    int   perm[N_];
};

// Full matching + loss for one batch resident in smem. Requires
// st.colkey[] == FULLM on entry (atomicMin identity; never reset inside —
// round invariant: every proposed column is matched in that round).
__device__ __forceinline__ float process_batch(Tiles& tl, MatchState& st,
                                               int lane)
{
    const int r0 = lane, r1 = lane + 32;
    // Stride 19 is coprime with 32 banks -> these LDS are conflict-free.
    const float a0 = tl.yt[r0 * F_ + 0];        // exactly 0.0f or 1.0f
    const float x0 = tl.yt[r0 * F_ + 1];
    const float a1 = tl.yt[r1 * F_ + 0];
    const float x1 = tl.yt[r1 * F_ + 1];

    // Active mask over 64 rows (alpha==1 only; phase 1 is eliminated).
    unsigned bl0 = __ballot_sync(FULLM, a0 > 0.5f);
    unsigned bl1 = __ballot_sync(FULLM, a1 > 0.5f);
    unsigned long long act = (unsigned long long)bl0 |
                             ((unsigned long long)bl1 << 32);

    st.pmneg[r0] = -tl.yp[r0 * F_ + 1];
    st.pmneg[r1] = -tl.yp[r1 * F_ + 1];
    __syncwarp();

    const unsigned long long* pm2 =
        (const unsigned long long*)st.pmneg;    // 8B-aligned pair view

    while (act) {
        const int      cnt = __popcll(act);
        const unsigned lo  = (unsigned)act;
        const unsigned hi  = (unsigned)(act >> 32);
        const int      plo = __popc(lo);

        int pr[2], pj[2];
        pr[0] = pr[1] = -1;
        unsigned long long kill = 0;

        // Proposal: lane takes the (base+lane)-th active row (ascending).
        for (int base = 0; base < cnt; base += 32) {
            const int t = base >> 5;
            const int i = base + lane;
            if (i < cnt) {
                const int r = (i < plo)
                            ? (int)__fns(lo, 0, i + 1)
                            : 32 + (int)__fns(hi, 0, i - plo + 1);
                const float xr = tl.yt[r * F_ + 1];   // LDS (2-way max)

                unsigned long long x2;
                asm("mov.b64 %0, {%1,%1};"
                    : "=l"(x2) : "r"(__float_as_uint(xr)));

                // argmin |x - p_j|: 8 independent chains of 4 pairs.
                // key32 = (|d| bits & ~63) | j -> IMNMX gives min |d|,
                // then lowest j (first-index ties, JAX argmax semantics).
                unsigned cb[8];
#pragma unroll
                for (int c = 0; c < 8; ++c) {
                    unsigned bc = FULLM;
#pragma unroll
                    for (int k = 0; k < 4; ++k) {
                        const int jj = c * 4 + k;            // pair index
                        unsigned long long d2 = f32x2_add(x2, pm2[jj]);
                        unsigned k0 = ((unsigned)d2        & 0x7FFFFFC0u)
                                    | (unsigned)(2 * jj);
                        unsigned k1 = ((unsigned)(d2 >> 32)& 0x7FFFFFC0u)
                                    | (unsigned)(2 * jj + 1);
                        bc = umin(bc, umin(k0, k1));
                    }
                    cb[c] = bc;
                }
                unsigned best = cb[0];
#pragma unroll
                for (int c = 1; c < 8; ++c) best = umin(best, cb[c]);

                const int bj = (int)(best & 63u);
                // 32-bit acceptance key: (masked |d| bits) | row.
                // NATIVE atomicMin.u32 = smallest distance, lowest row.
                atomicMin(&st.colkey[bj],
                          (best & 0x7FFFFFC0u) | (unsigned)r);
                pr[t] = r; pj[t] = bj;
            }
        }
        __syncwarp();                  // proposals visible warp-wide

        // Acceptance: min-key proposer of each proposed column wins,
        // poisons it, records perm, retires its row.
#pragma unroll
        for (int t = 0; t < 2; ++t) {
            const int r = pr[t];
            if (r >= 0) {
                const int bj = pj[t];
                if ((int)(st.colkey[bj] & 63u) == r) {
                    st.perm[r]   = bj;
                    st.pmneg[bj] = __uint_as_float(POISON_BITS); // -3.0f
                    kill |= 1ull << r;
                }
            }
        }
        // Combine retired rows via warp reduction (no smem mask).
#pragma unroll
        for (int o = 16; o; o >>= 1)
            kill |= __shfl_xor_sync(FULLM, kill, o);
        act &= ~kill;
        __syncwarp();                  // poison/perm visible next round
    }
    __syncwarp();

    // ---- Epilogue: pure LDS ----
    float term = 0.0f;
    if (a0 > 0.5f) {
        const float* gtr = &tl.yt[r0 * F_];
        const float* ypr = &tl.yp[st.perm[r0] * F_];
        const float d0 = 1.0f - ypr[0];
        const float dx = x0 - ypr[1];
        float sq = 0.0f;
#pragma unroll
        for (int f = 2; f < F_; ++f) {
            float d = gtr[f] - ypr[f];
            sq += d * d;
        }
        term += LAMBDA_COORD * dx * dx + d0 * d0 + sq;
    }
    if (a1 > 0.5f) {
        const float* gtr = &tl.yt[r1 * F_];
        const float* ypr = &tl.yp[st.perm[r1] * F_];
        const float d0 = 1.0f - ypr[0];
        const float dx = x1 - ypr[1];
        float sq = 0.0f;
#pragma unroll
        for (int f = 2; f < F_; ++f) {
            float d = gtr[f] - ypr[f];
            sq += d * d;
        }
        term += LAMBDA_COORD * dx * dx + d0 * d0 + sq;
    }
    // alpha=0 contribution per COLUMN: every column not taken in phase 0 is
    // assigned to exactly one alpha=0 row -> 0.5*yp[col,0]^2.
    if (__float_as_uint(st.pmneg[r0]) != POISON_BITS) {
        float p = tl.yp[r0 * F_ + 0];
        term += LAMBDA_NOOBJ * p * p;
    }
    if (__float_as_uint(st.pmneg[r1]) != POISON_BITS) {
        float p = tl.yp[r1 * F_ + 0];
        term += LAMBDA_NOOBJ * p * p;
    }
    return term;
}

__global__ __launch_bounds__(32 * WPB) void spotting_loss_kernel(
    const float* __restrict__ y_true,
    const float* __restrict__ y_pred,
    float* __restrict__ out,
    int batches)
{
    __shared__ Tiles      tiles[WPB][BPW];     // double-buffered tiles
    __shared__ MatchState mst[WPB];            // reused across the pair
    __shared__ float      red_s[WPB];

    const int w    = threadIdx.x >> 5;
    const int lane = threadIdx.x & 31;
    const int b0   = (blockIdx.x * WPB + w) * BPW;   // first batch of pair

    float term = 0.0f;

    // ---- Issue BOTH batches' staging up front: one commit group each ----
#pragma unroll
    for (int k = 0; k < BPW; ++k) {
        const int b = b0 + k;
        if (b < batches) {
            const char* g0 = (const char*)(y_true + (size_t)b * TILE_FLOATS);
            const char* g1 = (const char*)(y_pred + (size_t)b * TILE_FLOATS);
            uint32_t dt = (uint32_t)__cvta_generic_to_shared(tiles[w][k].yt);
            uint32_t dp = (uint32_t)__cvta_generic_to_shared(tiles[w][k].yp);
#pragma unroll
            for (int c = 0; c < 10; ++c) {            // 304 chunks per tile
                int idx = lane + c * 32;
                if (idx < TILE_CHUNKS) {
                    cp_async16(dt + idx * 16, g0 + idx * 16);
                    cp_async16(dp + idx * 16, g1 + idx * 16);
                }
            }
        }
        asm volatile("cp.async.commit_group;" ::: "memory");
    }

    mst[w].colkey[lane]      = FULLM;          // atomicMin identity
    mst[w].colkey[lane + 32] = FULLM;

    // ---- Batch A: ready after group 0 completes (1 group may pend) ----
    asm volatile("cp.async.wait_group 1;" ::: "memory");
    __syncwarp();
    if (b0 < batches)
        term += process_batch(tiles[w][0], mst[w], lane);

    // Re-arm acceptance keys for batch B (invariant holds per batch).
    mst[w].colkey[lane]      = FULLM;
    mst[w].colkey[lane + 32] = FULLM;

    // ---- Batch B: its stream drained under batch A's compute ----
    asm volatile("cp.async.wait_group 0;" ::: "memory");
    __syncwarp();
    if (b0 + 1 < batches)
        term += process_batch(tiles[w][1], mst[w], lane);

    // ---- Warp reduce -> block reduce -> ONE atomic + ticket per block ----
#pragma unroll
    for (int o = 16; o; o >>= 1) term += __shfl_down_sync(FULLM, term, o);
    if (lane == 0) red_s[w] = term;
    __syncthreads();                           // only block barrier

    if (threadIdx.x == 0) {
        float bsum = red_s[0] + red_s[1] + red_s[2] + red_s[3];
        atomicAdd(&g_acc, bsum);               // relaxed RED.ADD
        // acq_rel ticket: release orders our g_acc add before the increment;
        // acquire on the last block makes all other blocks' adds visible.
        unsigned ticket;
        asm volatile("atom.acq_rel.gpu.global.add.u32 %0, [%1], 1;"
                     : "=r"(ticket) : "l"(&g_count) : "memory");
        if (ticket == gridDim.x - 1) {         // last block finalizes
            float total;
            asm volatile("ld.acquire.gpu.global.f32 %0, [%1];"
                         : "=f"(total) : "l"(&g_acc) : "memory");
            out[0]  = total;
            g_acc   = 0.0f;                    // reset for next graph replay
            g_count = 0u;
        }
    }
}

extern "C" void kernel_launch(void* const* d_in, const int* in_sizes, int n_in,
                              void* d_out, int out_size)
{
    const float* y_true = (const float*)d_in[0];
    const float* y_pred = (const float*)d_in[1];
    float* out = (float*)d_out;

    int batches = in_sizes[0] / (N_ * F_);               // 2048
    int grid = (batches + WPB * BPW - 1) / (WPB * BPW);  // 256
    spotting_loss_kernel<<<grid, 32 * WPB>>>(y_true, y_pred, out, batches);
}